// round 15
// baseline (speedup 1.0000x reference)
#include <cuda_runtime.h>
#include <cuda_bf16.h>
#include <mma.h>
#include <math.h>

using namespace nvcuda;

#define Bn 65536
#define NP 2080        // 64*65/2 pairs i<=j
#define KB_BIL 2144    // 64 linear + 2080 pairs
#define KB_TOPO 768

// ---------- device scratch ----------
__device__ float g_cosd[64], g_Finv[4096], g_metric[4096], g_Wf[4096], g_bf[64];
__device__ float g_Dsym[NP * 64];
__device__ unsigned char g_pi[NP], g_pj[NP];
__device__ float g_WqT[4096], g_WkT[4096], g_WvT[4096], g_WoT[4096], g_WuT[4096], g_WsT[4096];
__device__ double g_aug[64 * 128];
__device__ float g_topo[64 * Bn], g_qv[64 * Bn], g_kv[64 * Bn], g_vv[64 * Bn];
__device__ float g_quant[64 * Bn], g_xm[64 * Bn];
// pre-split bf16 B tiles, row-major [k][64]
__device__ unsigned short g_topoBh[KB_TOPO * 64], g_topoBl[KB_TOPO * 64];
__device__ unsigned short g_bilBh[KB_BIL * 64], g_bilBl[KB_BIL * 64];

// ---------- packed f32x2 (fp32 middle kernels) ----------
typedef unsigned long long u64;
__device__ __forceinline__ u64 pk2(float lo, float hi) {
    u64 r; asm("mov.b64 %0, {%1, %2};" : "=l"(r) : "f"(lo), "f"(hi)); return r;
}
__device__ __forceinline__ void upk2(u64 v, float& lo, float& hi) {
    asm("mov.b64 {%0, %1}, %2;" : "=f"(lo), "=f"(hi) : "l"(v));
}
__device__ __forceinline__ u64 ffma2(u64 a, u64 b, u64 c) {
    u64 d; asm("fma.rn.f32x2 %0, %1, %2, %3;" : "=l"(d) : "l"(a), "l"(b), "l"(c)); return d;
}
__device__ __forceinline__ void gemv32(const float* xsh, const float* W, int lt, int ob,
                                       u64 acc[16]) {
#pragma unroll 4
    for (int i = 0; i < 64; i++) {
        float x = xsh[i * 128 + lt];
        u64 xv = pk2(x, x);
        const ulonglong2* row = (const ulonglong2*)(W + i * 64 + ob);
#pragma unroll
        for (int q = 0; q < 8; q++) {
            ulonglong2 w = row[q];
            acc[2 * q] = ffma2(xv, w.x, acc[2 * q]);
            acc[2 * q + 1] = ffma2(xv, w.y, acc[2 * q + 1]);
        }
    }
}
__device__ __forceinline__ void gemv32x2(const float* xsh, const float* W, int lt, int ob,
                                         u64 a1[16], u64 a2[16]) {
#pragma unroll 2
    for (int i = 0; i < 64; i++) {
        float x1 = xsh[i * 256 + lt], x2 = xsh[i * 256 + 128 + lt];
        u64 v1 = pk2(x1, x1), v2 = pk2(x2, x2);
        const ulonglong2* row = (const ulonglong2*)(W + i * 64 + ob);
#pragma unroll
        for (int q = 0; q < 8; q++) {
            ulonglong2 w = row[q];
            a1[2 * q] = ffma2(v1, w.x, a1[2 * q]);
            a1[2 * q + 1] = ffma2(v1, w.y, a1[2 * q + 1]);
            a2[2 * q] = ffma2(v2, w.x, a2[2 * q]);
            a2[2 * q + 1] = ffma2(v2, w.y, a2[2 * q + 1]);
        }
    }
}

#define STAGE(dst, src, n4)                                    \
    do {                                                       \
        __syncthreads();                                       \
        for (int _i = tid; _i < (n4); _i += 256)               \
            ((float4*)(dst))[_i] = ((const float4*)(src))[_i]; \
        __syncthreads();                                       \
    } while (0)

__device__ __forceinline__ unsigned int bsplit_pack(float a, float b) {
    // pack bf16(hi parts) of two values
    __nv_bfloat16 ha = __float2bfloat16(a), hb = __float2bfloat16(b);
    return (unsigned int)__bfloat16_as_ushort(ha) |
           ((unsigned int)__bfloat16_as_ushort(hb) << 16);
}
__device__ __forceinline__ void bsplit2(float a, float b, unsigned int& hi, unsigned int& lo) {
    __nv_bfloat16 ha = __float2bfloat16(a), hb = __float2bfloat16(b);
    float ra = a - __bfloat162float(ha), rb = b - __bfloat162float(hb);
    __nv_bfloat16 la = __float2bfloat16(ra), lb = __float2bfloat16(rb);
    hi = (unsigned int)__bfloat16_as_ushort(ha) | ((unsigned int)__bfloat16_as_ushort(hb) << 16);
    lo = (unsigned int)__bfloat16_as_ushort(la) | ((unsigned int)__bfloat16_as_ushort(lb) << 16);
}

// ============ K0a: single-CTA precompute ============
__global__ void k0a(const float* __restrict__ phase, const float* __restrict__ q_w,
                    const float* __restrict__ k_w, const float* __restrict__ v_w,
                    const float* __restrict__ o_w, const float* __restrict__ update_w,
                    const float* __restrict__ state_w, const float* __restrict__ fisher_m,
                    const float* __restrict__ metric_m, const float* __restrict__ proj_w,
                    const float* __restrict__ proj_b, const float* __restrict__ obj_emb,
                    const float* __restrict__ morphisms, const float* __restrict__ functor_w,
                    const float* __restrict__ out_w, const float* __restrict__ out_b) {
    __shared__ float s_a[4096], s_b[4096], s_fw[64];
    __shared__ double s_f[64], s_bv[2], s_pv;
    __shared__ int s_br[2], s_piv;
    int tid = threadIdx.x;
    if (tid < 64) g_cosd[tid] = cosf(phase[tid >> 3] - phase[tid & 7]);
    for (int idx = tid; idx < 4096; idx += 256) {
        int o = idx >> 6, i = idx & 63;
        g_WqT[i * 64 + o] = q_w[idx];  g_WkT[i * 64 + o] = k_w[idx];
        g_WvT[i * 64 + o] = v_w[idx];  g_WoT[i * 64 + o] = o_w[idx];
        g_WuT[i * 64 + o] = update_w[o * 128 + i];  // h0=0: only first half
        g_WsT[i * 64 + o] = state_w[o * 128 + i];
    }
    for (int idx = tid; idx < 4096; idx += 256) {
        int i = idx >> 6, j = idx & 63;
        float sf = 0.f, sm = 0.f;
        for (int k = 0; k < 64; k++) {
            sf += fisher_m[i * 64 + k] * fisher_m[j * 64 + k];
            sm += metric_m[i * 64 + k] * metric_m[j * 64 + k];
        }
        g_metric[idx] = sm;
        g_aug[i * 128 + j] = (double)sf;
        g_aug[i * 128 + 64 + j] = (j == i) ? 1.0 : 0.0;
    }
    if (tid == 0) {
        int p = 0;
        for (int i = 0; i < 64; i++)
            for (int j = i; j < 64; j++) { g_pi[p] = i; g_pj[p] = j; p++; }
    }
    __syncthreads();
    for (int col = 0; col < 64; col++) {
        if (tid < 64) {
            double v = (tid >= col) ? fabs(g_aug[tid * 128 + col]) : -1.0;
            int r = tid;
            for (int off = 16; off; off >>= 1) {
                double ov = __shfl_down_sync(0xffffffffu, v, off);
                int orr = __shfl_down_sync(0xffffffffu, r, off);
                if (ov > v) { v = ov; r = orr; }
            }
            if ((tid & 31) == 0) { s_bv[tid >> 5] = v; s_br[tid >> 5] = r; }
        }
        __syncthreads();
        if (tid == 0) s_piv = (s_bv[1] > s_bv[0]) ? s_br[1] : s_br[0];
        __syncthreads();
        int piv = s_piv;
        int ncol = 128 - col;
        if (piv != col && tid < ncol) {
            int c = col + tid;
            double t = g_aug[piv * 128 + c];
            g_aug[piv * 128 + c] = g_aug[col * 128 + c];
            g_aug[col * 128 + c] = t;
        }
        __syncthreads();
        if (tid == 0) s_pv = g_aug[col * 128 + col];
        __syncthreads();
        if (tid < ncol) g_aug[col * 128 + col + tid] /= s_pv;
        __syncthreads();
        if (tid < 64) s_f[tid] = (tid == col) ? 0.0 : g_aug[tid * 128 + col];
        __syncthreads();
        int total = 64 * ncol;
        for (int t = tid; t < total; t += 256) {
            int r = t / ncol, c = col + (t - r * ncol);
            g_aug[r * 128 + c] -= s_f[r] * g_aug[col * 128 + c];
        }
        __syncthreads();
    }
    for (int idx = tid; idx < 4096; idx += 256)
        g_Finv[idx] = (float)g_aug[(idx >> 6) * 128 + 64 + (idx & 63)];
    if (tid == 0) {
        float m = functor_w[0];
        for (int i = 1; i < 64; i++) m = fmaxf(m, functor_w[i]);
        float s = 0.f;
        for (int i = 0; i < 64; i++) { float e = expf(functor_w[i] - m); s_fw[i] = e; s += e; }
        for (int i = 0; i < 64; i++) s_fw[i] /= s;
    }
    __syncthreads();
    for (int idx = tid; idx < 4096; idx += 256) {
        float s = 0.f;
        for (int m = 0; m < 64; m++) s += s_fw[m] * morphisms[m * 4096 + idx];
        s_a[idx] = s;
    }
    __syncthreads();
    for (int idx = tid; idx < 4096; idx += 256) {
        int k = idx >> 6, j = idx & 63;
        float s = 0.f;
        for (int i = 0; i < 64; i++) s += obj_emb[k * 64 + i] * s_a[i * 64 + j];
        s_b[idx] = s;
    }
    __syncthreads();
    for (int idx = tid; idx < 4096; idx += 256) {
        int k = idx >> 6, o = idx & 63;
        float s = 0.f;
        for (int j = 0; j < 64; j++) s += s_b[k * 64 + j] * out_w[o * 64 + j];
        s_a[idx] = s;
    }
    __syncthreads();
    for (int idx = tid; idx < 4096; idx += 256) {
        int t = idx >> 6, o = idx & 63;
        float s = 0.f;
        for (int k = 0; k < 64; k++) s += proj_w[k * 64 + t] * s_a[k * 64 + o];
        g_Wf[idx] = s;
    }
    if (tid < 64) {
        float s = out_b[tid];
        for (int k = 0; k < 64; k++) s += proj_b[k] * s_a[k * 64 + tid];
        g_bf[tid] = s;
    }
}

// ============ K0b: Dsym[p][o] = sum_k (C[i,j,k]+C[j,i,k]) * Wf[k][o] ============
__global__ void k0b(const float* __restrict__ conn) {
    __shared__ float Wsh[4096];
    int tid = threadIdx.x;
    for (int idx = tid; idx < 4096; idx += 256) Wsh[idx] = g_Wf[idx];
    __syncthreads();
    int idx = blockIdx.x * 256 + tid;
    int p = idx >> 6, o = idx & 63;
    int i = g_pi[p], j = g_pj[p];
    const float* c1 = conn + (i * 64 + j) * 64;
    const float* c2 = conn + (j * 64 + i) * 64;
    float s = 0.f;
    if (i == j) { for (int k = 0; k < 64; k++) s += c1[k] * Wsh[k * 64 + o]; }
    else { for (int k = 0; k < 64; k++) s += (c1[k] + c2[k]) * Wsh[k * 64 + o]; }
    g_Dsym[idx] = s;
}

// ============ K0d: build bil B tiles (bf16 split, row-major [k][64]) ============
__global__ void k0d() {
    int idx = blockIdx.x * 256 + threadIdx.x;  // KB_BIL*64
    int r = idx >> 6, n = idx & 63;
    float v = (r < 64) ? g_Wf[r * 64 + n] : g_Dsym[(r - 64) * 64 + n];
    __nv_bfloat16 h = __float2bfloat16(v);
    __nv_bfloat16 l = __float2bfloat16(v - __bfloat162float(h));
    g_bilBh[idx] = __bfloat16_as_ushort(h);
    g_bilBl[idx] = __bfloat16_as_ushort(l);
}

// ============ K0e: build topo B tiles from tk ============
__global__ void k0e(const float* __restrict__ tk) {
    int idx = blockIdx.x * 256 + threadIdx.x;  // KB_TOPO*64
    int jd = idx >> 6, n = idx & 63;
    float v = tk[n * 768 + jd];
    __nv_bfloat16 h = __float2bfloat16(v);
    __nv_bfloat16 l = __float2bfloat16(v - __bfloat162float(h));
    g_topoBh[idx] = __bfloat16_as_ushort(h);
    g_topoBl[idx] = __bfloat16_as_ushort(l);
}

// ---------- shared WMMA tile geometry ----------
#define A_LD 40    // bf16 elems per A row (32 + pad)
#define B_LD 72    // bf16 elems per B row (64 + pad)
#define O_LD 68    // f32 elems per out row (64 + pad)

// ============ K1: topo via WMMA (tile 64 batch) ============
// smem: A_hi@0(5120) A_lo@5120(5120) B_hi@10240(4608) B_lo@14848(4608) out@19456(17408)
__global__ void __launch_bounds__(256, 2) k_topo3(const float* __restrict__ pers) {
    extern __shared__ char smem[];
    __nv_bfloat16* Ah = (__nv_bfloat16*)(smem);
    __nv_bfloat16* Al = (__nv_bfloat16*)(smem + 5120);
    __nv_bfloat16* Bh = (__nv_bfloat16*)(smem + 10240);
    __nv_bfloat16* Bl = (__nv_bfloat16*)(smem + 14848);
    float* outS = (float*)(smem + 19456);
    int tid = threadIdx.x, wid = tid >> 5;
    int b0 = blockIdx.x * 64;
    int mt = wid >> 1, nh = wid & 1;

    wmma::fragment<wmma::accumulator, 16, 16, 16, float> cf[2];
    wmma::fill_fragment(cf[0], 0.0f);
    wmma::fill_fragment(cf[1], 0.0f);

    for (int c = 0; c < KB_TOPO / 32; c++) {
        int c0 = c * 32;
        // B copy: 32 rows x 64 cols (as u32 pairs)
        for (int i = tid; i < 1024; i += 256) {
            int kk = i >> 5, cc = i & 31;
            ((unsigned int*)(Bh + kk * B_LD))[cc] =
                ((const unsigned int*)(g_topoBh + (c0 + kk) * 64))[cc];
            ((unsigned int*)(Bl + kk * B_LD))[cc] =
                ((const unsigned int*)(g_topoBl + (c0 + kk) * 64))[cc];
        }
        // A staging: 64 rows x 32 k (2 per thread-iter)
        for (int i = tid; i < 1024; i += 256) {
            int m = i >> 4, kk2 = i & 15;
            int jd0 = c0 + 2 * kk2;
            int j0 = jd0 / 3, d0 = jd0 - j0 * 3;
            int jd1 = jd0 + 1;
            int j1 = jd1 / 3, d1 = jd1 - j1 * 3;
            float2 t0 = __ldcs((const float2*)(pers + (((size_t)j0 * Bn + b0 + m) * 3 + d0) * 2));
            float2 t1 = __ldcs((const float2*)(pers + (((size_t)j1 * Bn + b0 + m) * 3 + d1) * 2));
            unsigned int hi, lo;
            bsplit2(t0.x + t0.y, t1.x + t1.y, hi, lo);
            ((unsigned int*)(Ah + m * A_LD))[kk2] = hi;
            ((unsigned int*)(Al + m * A_LD))[kk2] = lo;
        }
        __syncthreads();
#pragma unroll
        for (int ks = 0; ks < 2; ks++) {
            int kk0 = ks * 16;
            wmma::fragment<wmma::matrix_a, 16, 16, 16, __nv_bfloat16, wmma::row_major> ah, al;
            wmma::load_matrix_sync(ah, Ah + mt * 16 * A_LD + kk0, A_LD);
            wmma::load_matrix_sync(al, Al + mt * 16 * A_LD + kk0, A_LD);
#pragma unroll
            for (int t = 0; t < 2; t++) {
                wmma::fragment<wmma::matrix_b, 16, 16, 16, __nv_bfloat16, wmma::row_major> bh, bl;
                int n0 = nh * 32 + t * 16;
                wmma::load_matrix_sync(bh, Bh + kk0 * B_LD + n0, B_LD);
                wmma::load_matrix_sync(bl, Bl + kk0 * B_LD + n0, B_LD);
                wmma::mma_sync(cf[t], ah, bh, cf[t]);
                wmma::mma_sync(cf[t], ah, bl, cf[t]);
                wmma::mma_sync(cf[t], al, bh, cf[t]);
            }
        }
        __syncthreads();
    }
    // store col-major: outS[m + n*O_LD]
#pragma unroll
    for (int t = 0; t < 2; t++)
        wmma::store_matrix_sync(outS + mt * 16 + (nh * 32 + t * 16) * O_LD, cf[t], O_LD,
                                wmma::mem_col_major);
    __syncthreads();
    for (int i = tid; i < 1024; i += 256) {
        int o = i >> 4, mq = (i & 15) * 4;
        float4 v = *(const float4*)(outS + o * O_LD + mq);
        *(float4*)(g_topo + (size_t)o * Bn + b0 + mq) = v;
    }
}

// ============ K2: q/k/v (fp32, unchanged) ============
__global__ void __launch_bounds__(256, 2) k_qkv(const float* __restrict__ qb,
                                                const float* __restrict__ kb,
                                                const float* __restrict__ vb) {
    extern __shared__ float sm[];
    float* in_sh = sm;
    float* buf = sm + 16384;
    __shared__ float bsh[192];
    int tid = threadIdx.x, lt = tid & 127, ob = (tid >> 7) * 32;
    int b0 = blockIdx.x * 256, b = b0 + lt;
    if (tid < 64) { bsh[tid] = qb[tid]; bsh[64 + tid] = kb[tid]; bsh[128 + tid] = vb[tid]; }
    for (int idx = tid; idx < 16384; idx += 256)
        in_sh[idx] = g_topo[(idx >> 8) * Bn + b0 + (idx & 255)];
    const float* Wg[3] = {g_WqT, g_WkT, g_WvT};
    float* outg[3] = {g_qv, g_kv, g_vv};
    for (int s = 0; s < 3; s++) {
        STAGE(buf, Wg[s], 1024);
        u64 a1[16], a2[16];
#pragma unroll
        for (int q = 0; q < 16; q++) { a1[q] = 0ull; a2[q] = 0ull; }
        gemv32x2(in_sh, buf, lt, ob, a1, a2);
#pragma unroll
        for (int q = 0; q < 16; q++) {
            float lo, hi;
            float b1 = bsh[s * 64 + ob + 2 * q], b2 = bsh[s * 64 + ob + 2 * q + 1];
            upk2(a1[q], lo, hi);
            outg[s][(ob + 2 * q) * Bn + b] = lo + b1;
            outg[s][(ob + 2 * q + 1) * Bn + b] = hi + b2;
            upk2(a2[q], lo, hi);
            outg[s][(ob + 2 * q) * Bn + b + 128] = lo + b1;
            outg[s][(ob + 2 * q + 1) * Bn + b + 128] = hi + b2;
        }
    }
}

// ============ K3: attention + o-proj (fp32, unchanged) ============
__global__ void __launch_bounds__(256, 2) k_att(const float* __restrict__ ob_bias) {
    extern __shared__ float sm[];
    float* k_sh = sm;
    float* v_sh = sm + 8192;
    float* buf = sm + 16384;
    __shared__ float cos_sh[64], obb[64];
    int tid = threadIdx.x, lt = tid & 127, ob = (tid >> 7) * 32;
    int b0 = blockIdx.x * 128, b = b0 + lt;
    if (tid < 64) { cos_sh[tid] = g_cosd[tid]; obb[tid] = ob_bias[tid]; }
    for (int idx = tid; idx < 8192; idx += 256) {
        int i = idx >> 7, c = idx & 127;
        k_sh[idx] = g_kv[i * Bn + b0 + c];
        v_sh[idx] = g_vv[i * Bn + b0 + c];
    }
    STAGE(buf, g_WoT, 1024);
    u64 acc[16];
#pragma unroll
    for (int q = 0; q < 16; q++) acc[q] = 0ull;
    for (int h = 0; h < 8; h++) {
        float qh[8];
#pragma unroll
        for (int d = 0; d < 8; d++) qh[d] = g_qv[(h * 8 + d) * Bn + b];
        float s[8];
#pragma unroll
        for (int g = 0; g < 8; g++) {
            float dot = 0.f;
#pragma unroll
            for (int d = 0; d < 8; d++) dot += qh[d] * k_sh[(g * 8 + d) * 128 + lt];
            s[g] = dot * cos_sh[h * 8 + g] * 0.35355339059327373f;
        }
        float m = s[0];
#pragma unroll
        for (int g = 1; g < 8; g++) m = fmaxf(m, s[g]);
        float sum = 0.f;
#pragma unroll
        for (int g = 0; g < 8; g++) { s[g] = expf(s[g] - m); sum += s[g]; }
        float inv = 1.0f / sum;
        float av8[8] = {0, 0, 0, 0, 0, 0, 0, 0};
#pragma unroll
        for (int g = 0; g < 8; g++) {
            float w = s[g] * inv;
#pragma unroll
            for (int d = 0; d < 8; d++) av8[d] += w * v_sh[(g * 8 + d) * 128 + lt];
        }
#pragma unroll
        for (int d = 0; d < 8; d++) {
            u64 xv = pk2(av8[d], av8[d]);
            const ulonglong2* row = (const ulonglong2*)(buf + (h * 8 + d) * 64 + ob);
#pragma unroll
            for (int q = 0; q < 8; q++) {
                ulonglong2 w = row[q];
                acc[2 * q] = ffma2(xv, w.x, acc[2 * q]);
                acc[2 * q + 1] = ffma2(xv, w.y, acc[2 * q + 1]);
            }
        }
    }
#pragma unroll
    for (int q = 0; q < 16; q++) {
        float lo, hi; upk2(acc[q], lo, hi);
        g_quant[(ob + 2 * q) * Bn + b] = lo + obb[ob + 2 * q];
        g_quant[(ob + 2 * q + 1) * Bn + b] = hi + obb[ob + 2 * q + 1];
    }
}

// ============ K4: update+cand+Finv+metric fused (fp32, unchanged) ============
__global__ void __launch_bounds__(256, 2) k_ucx(const float* __restrict__ ub,
                                                const float* __restrict__ sb) {
    extern __shared__ float sm[];
    float* in_sh = sm;
    float* c_sh = sm + 8192;
    float* buf = sm + 16384;
    __shared__ float bsh[128];
    int tid = threadIdx.x, lt = tid & 127, ob = (tid >> 7) * 32;
    int b0 = blockIdx.x * 128, b = b0 + lt;
    if (tid < 64) { bsh[tid] = ub[tid]; bsh[64 + tid] = sb[tid]; }
    for (int idx = tid; idx < 8192; idx += 256)
        in_sh[idx] = g_quant[(idx >> 7) * Bn + b0 + (idx & 127)];
    STAGE(buf, g_WuT, 1024);
    u64 acc[16];
#pragma unroll
    for (int q = 0; q < 16; q++) acc[q] = 0ull;
    gemv32(in_sh, buf, lt, ob, acc);
    float ur[32];
#pragma unroll
    for (int q = 0; q < 16; q++) {
        float lo, hi; upk2(acc[q], lo, hi);
        ur[2 * q] = 1.0f / (1.0f + expf(-(lo + bsh[ob + 2 * q])));
        ur[2 * q + 1] = 1.0f / (1.0f + expf(-(hi + bsh[ob + 2 * q + 1])));
    }
    STAGE(buf, g_WsT, 1024);
#pragma unroll
    for (int q = 0; q < 16; q++) acc[q] = 0ull;
    gemv32(in_sh, buf, lt, ob, acc);
#pragma unroll
    for (int q = 0; q < 16; q++) {
        float lo, hi; upk2(acc[q], lo, hi);
        c_sh[(ob + 2 * q) * 128 + lt] = tanhf(lo + bsh[64 + ob + 2 * q]);
        c_sh[(ob + 2 * q + 1) * 128 + lt] = tanhf(hi + bsh[64 + ob + 2 * q + 1]);
    }
    STAGE(buf, g_Finv, 1024);
#pragma unroll
    for (int q = 0; q < 16; q++) acc[q] = 0ull;
    gemv32(c_sh, buf, lt, ob, acc);
#pragma unroll
    for (int q = 0; q < 16; q++) {
        float lo, hi; upk2(acc[q], lo, hi);
        in_sh[(ob + 2 * q) * 128 + lt] = lo * ur[2 * q];
        in_sh[(ob + 2 * q + 1) * 128 + lt] = hi * ur[2 * q + 1];
    }
    STAGE(buf, g_metric, 1024);
#pragma unroll
    for (int q = 0; q < 16; q++) acc[q] = 0ull;
    gemv32(in_sh, buf, lt, ob, acc);
#pragma unroll
    for (int q = 0; q < 16; q++) {
        float lo, hi; upk2(acc[q], lo, hi);
        g_xm[(ob + 2 * q) * Bn + b] = lo;
        g_xm[(ob + 2 * q + 1) * Bn + b] = hi;
    }
}

// ============ K5: bilinear + tail via WMMA (tile 64 batch) ============
// smem: xm@0(16384) pi@16384(2080) pj@18464(2080) bf@20544(256)
//       A_hi@20800(5120) A_lo@25920(5120) B_hi@31040(4608) B_lo@35648(4608)
//       out@40256(17408)  total 57664
__global__ void __launch_bounds__(256, 2) k_bil3(float* __restrict__ out) {
    extern __shared__ char smem[];
    float* xm_sh = (float*)(smem);
    unsigned char* pi_sh = (unsigned char*)(smem + 16384);
    unsigned char* pj_sh = (unsigned char*)(smem + 18464);
    float* bf_sh = (float*)(smem + 20544);
    __nv_bfloat16* Ah = (__nv_bfloat16*)(smem + 20800);
    __nv_bfloat16* Al = (__nv_bfloat16*)(smem + 25920);
    __nv_bfloat16* Bh = (__nv_bfloat16*)(smem + 31040);
    __nv_bfloat16* Bl = (__nv_bfloat16*)(smem + 35648);
    float* outS = (float*)(smem + 40256);
    int tid = threadIdx.x, wid = tid >> 5;
    int b0 = blockIdx.x * 64;
    int mt = wid >> 1, nh = wid & 1;

    for (int i = tid; i < NP; i += 256) { pi_sh[i] = g_pi[i]; pj_sh[i] = g_pj[i]; }
    if (tid < 64) bf_sh[tid] = g_bf[tid];
    for (int i = tid; i < 4096; i += 256)
        xm_sh[i] = g_xm[(i >> 6) * Bn + b0 + (i & 63)];
    __syncthreads();

    wmma::fragment<wmma::accumulator, 16, 16, 16, float> cf[2];
    wmma::fill_fragment(cf[0], 0.0f);
    wmma::fill_fragment(cf[1], 0.0f);

    for (int c = 0; c < KB_BIL / 32; c++) {
        int c0 = c * 32;
        for (int i = tid; i < 1024; i += 256) {
            int kk = i >> 5, cc = i & 31;
            ((unsigned int*)(Bh + kk * B_LD))[cc] =
                ((const unsigned int*)(g_bilBh + (c0 + kk) * 64))[cc];
            ((unsigned int*)(Bl + kk * B_LD))[cc] =
                ((const unsigned int*)(g_bilBl + (c0 + kk) * 64))[cc];
        }
        for (int i = tid; i < 1024; i += 256) {
            int m = i >> 4, kk2 = i & 15;
            int r0 = c0 + 2 * kk2;
            float v0, v1;
            if (r0 < 64) {
                v0 = xm_sh[r0 * 64 + m];
                v1 = xm_sh[(r0 + 1) * 64 + m];
            } else {
                int p0 = r0 - 64, p1 = p0 + 1;
                v0 = xm_sh[pi_sh[p0] * 64 + m] * xm_sh[pj_sh[p0] * 64 + m];
                v1 = xm_sh[pi_sh[p1] * 64 + m] * xm_sh[pj_sh[p1] * 64 + m];
            }
            unsigned int hi, lo;
            bsplit2(v0, v1, hi, lo);
            ((unsigned int*)(Ah + m * A_LD))[kk2] = hi;
            ((unsigned int*)(Al + m * A_LD))[kk2] = lo;
        }
        __syncthreads();
#pragma unroll
        for (int ks = 0; ks < 2; ks++) {
            int kk0 = ks * 16;
            wmma::fragment<wmma::matrix_a, 16, 16, 16, __nv_bfloat16, wmma::row_major> ah, al;
            wmma::load_matrix_sync(ah, Ah + mt * 16 * A_LD + kk0, A_LD);
            wmma::load_matrix_sync(al, Al + mt * 16 * A_LD + kk0, A_LD);
#pragma unroll
            for (int t = 0; t < 2; t++) {
                wmma::fragment<wmma::matrix_b, 16, 16, 16, __nv_bfloat16, wmma::row_major> bh, bl;
                int n0 = nh * 32 + t * 16;
                wmma::load_matrix_sync(bh, Bh + kk0 * B_LD + n0, B_LD);
                wmma::load_matrix_sync(bl, Bl + kk0 * B_LD + n0, B_LD);
                wmma::mma_sync(cf[t], ah, bh, cf[t]);
                wmma::mma_sync(cf[t], ah, bl, cf[t]);
                wmma::mma_sync(cf[t], al, bh, cf[t]);
            }
        }
        __syncthreads();
    }
#pragma unroll
    for (int t = 0; t < 2; t++)
        wmma::store_matrix_sync(outS + mt * 16 * O_LD + nh * 32 + t * 16, cf[t], O_LD,
                                wmma::mem_row_major);
    __syncthreads();
    for (int i = tid; i < 1024; i += 256) {
        int m = i >> 4, q = i & 15;
        float4 v = *(const float4*)(outS + m * O_LD + 4 * q);
        float4 bb = *(const float4*)(bf_sh + 4 * q);
        *(float4*)(out + (size_t)(b0 + m) * 64 + 4 * q) =
            make_float4(v.x + bb.x, v.y + bb.y, v.z + bb.z, v.w + bb.w);
    }
}

extern "C" void kernel_launch(void* const* d_in, const int* in_sizes, int n_in,
                              void* d_out, int out_size) {
    const float* pers     = (const float*)d_in[1];
    const float* tk       = (const float*)d_in[2];
    const float* q_w = (const float*)d_in[3],  *q_b = (const float*)d_in[4];
    const float* k_w = (const float*)d_in[5],  *k_b = (const float*)d_in[6];
    const float* v_w = (const float*)d_in[7],  *v_b = (const float*)d_in[8];
    const float* o_w = (const float*)d_in[9],  *o_b = (const float*)d_in[10];
    const float* phase = (const float*)d_in[11];
    const float* update_w = (const float*)d_in[12], *update_b = (const float*)d_in[13];
    const float* state_w  = (const float*)d_in[16], *state_b  = (const float*)d_in[17];
    const float* fisher_m = (const float*)d_in[18];
    const float* metric_m = (const float*)d_in[19];
    const float* connection = (const float*)d_in[20];
    const float* proj_w = (const float*)d_in[21], *proj_b = (const float*)d_in[22];
    const float* obj_emb = (const float*)d_in[23];
    const float* morphisms = (const float*)d_in[24];
    const float* functor_w = (const float*)d_in[25];
    const float* out_w = (const float*)d_in[26], *out_b = (const float*)d_in[27];
    float* out = (float*)d_out;

    static bool inited = false;
    static cudaStream_t s2;
    static cudaEvent_t ev1, ev2;
    if (!inited) {
        cudaFuncSetAttribute(k_topo3, cudaFuncAttributeMaxDynamicSharedMemorySize, 36864);
        cudaFuncSetAttribute(k_bil3, cudaFuncAttributeMaxDynamicSharedMemorySize, 57664);
        cudaFuncSetAttribute(k_qkv, cudaFuncAttributeMaxDynamicSharedMemorySize, 20480 * 4);
        cudaFuncSetAttribute(k_att, cudaFuncAttributeMaxDynamicSharedMemorySize, 20480 * 4);
        cudaFuncSetAttribute(k_ucx, cudaFuncAttributeMaxDynamicSharedMemorySize, 20480 * 4);
        cudaStreamCreateWithFlags(&s2, cudaStreamNonBlocking);
        cudaEventCreateWithFlags(&ev1, cudaEventDisableTiming);
        cudaEventCreateWithFlags(&ev2, cudaEventDisableTiming);
        inited = true;
    }
    // fork: weight precompute overlaps the big topo stream
    cudaEventRecord(ev1, 0);
    cudaStreamWaitEvent(s2, ev1, 0);
    k0a<<<1, 256, 0, s2>>>(phase, q_w, k_w, v_w, o_w, update_w, state_w, fisher_m,
                           metric_m, proj_w, proj_b, obj_emb, morphisms, functor_w,
                           out_w, out_b);
    k0b<<<NP * 64 / 256, 256, 0, s2>>>(connection);
    k0d<<<KB_BIL * 64 / 256, 256, 0, s2>>>();
    cudaEventRecord(ev2, s2);
    k0e<<<KB_TOPO * 64 / 256, 256>>>(tk);
    k_topo3<<<Bn / 64, 256, 36864>>>(pers);
    cudaStreamWaitEvent(0, ev2, 0);  // join before weight-dependent stages
    k_qkv<<<Bn / 256, 256, 20480 * 4>>>(q_b, k_b, v_b);
    k_att<<<Bn / 128, 256, 20480 * 4>>>(o_b);
    k_ucx<<<Bn / 128, 256, 20480 * 4>>>(update_b, state_b);
    k_bil3<<<Bn / 64, 256, 57664>>>(out);
}